// round 4
// baseline (speedup 1.0000x reference)
#include <cuda_runtime.h>
#include <math.h>

// Problem constants
#define NHEADS 6
#define HS     24
#define NE     144      // N_EMBD = NHEADS*HS
#define TT     128      // sequence length
#define MAXB   256      // batch

// Scratch (allocation-free: __device__ globals)
__device__ float g_q[MAXB * TT * NE];
__device__ float g_k[MAXB * TT * NE];
__device__ float g_v[MAXB * TT * NE];
__device__ float g_ctx[MAXB * TT * NE];

// ---------------------------------------------------------------------------
// GEMM: C[M,144] = A[M,144] @ W[144,144] (+bias). M = B*T = 32768.
// BM=128, BN=48, BK=48, 256 threads, 8x3 microtile per thread.
// ---------------------------------------------------------------------------
#define BM 128
#define BN 48
#define BK 48

__device__ __forceinline__ void gemm_body(const float* __restrict__ A,
                                          const float* __restrict__ W,
                                          const float* __restrict__ bias,
                                          float* __restrict__ C) {
    __shared__ float As[BM][BK + 4];   // stride 52 (16B aligned rows)
    __shared__ float Ws[BK][BN];

    const int tid = threadIdx.x;
    const int bm = blockIdx.x * BM;
    const int bn = blockIdx.y * BN;

    float acc[8][3];
#pragma unroll
    for (int i = 0; i < 8; i++) {
#pragma unroll
        for (int j = 0; j < 3; j++) acc[i][j] = 0.f;
    }

    for (int k0 = 0; k0 < NE; k0 += BK) {
        // A tile: 128x48 = 1536 float4, 6 per thread
#pragma unroll
        for (int i = 0; i < 6; i++) {
            int idx = tid + i * 256;
            int r = idx / 12, c4 = idx % 12;
            *(float4*)&As[r][c4 * 4] =
                *(const float4*)(A + (size_t)(bm + r) * NE + k0 + c4 * 4);
        }
        // W tile: 48x48 = 576 float4
        for (int idx = tid; idx < 576; idx += 256) {
            int r = idx / 12, c4 = idx % 12;
            *(float4*)&Ws[r][c4 * 4] =
                *(const float4*)(W + (size_t)(k0 + r) * NE + bn + c4 * 4);
        }
        __syncthreads();

        const int tx = tid & 15;   // 16 n-groups of 3
        const int ty = tid >> 4;   // 16 m-groups of 8
#pragma unroll
        for (int k = 0; k < BK; k++) {
            float a[8], b[3];
#pragma unroll
            for (int i = 0; i < 8; i++) a[i] = As[ty * 8 + i][k];
#pragma unroll
            for (int j = 0; j < 3; j++) b[j] = Ws[k][tx * 3 + j];
#pragma unroll
            for (int i = 0; i < 8; i++) {
#pragma unroll
                for (int j = 0; j < 3; j++) acc[i][j] = fmaf(a[i], b[j], acc[i][j]);
            }
        }
        __syncthreads();
    }

    const int tx = tid & 15;
    const int ty = tid >> 4;
#pragma unroll
    for (int j = 0; j < 3; j++) {
        float bb = bias ? bias[bn + tx * 3 + j] : 0.f;
#pragma unroll
        for (int i = 0; i < 8; i++) {
            C[(size_t)(bm + ty * 8 + i) * NE + bn + tx * 3 + j] = acc[i][j] + bb;
        }
    }
}

__global__ void __launch_bounds__(256) gemm_qkv_kernel(const float* __restrict__ x,
                                                       const float* __restrict__ Wq,
                                                       const float* __restrict__ Wk,
                                                       const float* __restrict__ Wv) {
    const float* W = (blockIdx.z == 0) ? Wq : (blockIdx.z == 1) ? Wk : Wv;
    float* C = (blockIdx.z == 0) ? g_q : (blockIdx.z == 1) ? g_k : g_v;
    gemm_body(x, W, nullptr, C);
}

__global__ void __launch_bounds__(256) gemm_proj_kernel(const float* __restrict__ Wp,
                                                        const float* __restrict__ bp,
                                                        float* __restrict__ out) {
    gemm_body(g_ctx, Wp, bp, out);
}

// ---------------------------------------------------------------------------
// Attention: one block per (b,h), 128 threads, one t-row per thread.
// Flash-style online softmax in chunks of 16 s-values. Per-warp causal skip.
// q[b,h,t,d] = flat[b*18432 + h*3072 + t*24 + d]  (raw reshape, NOT transpose)
//
// Smem: K (128x24) + V (128x24) + rel TRANSPOSED as RsT[d][row] with row
// stride 256 -> lane-consecutive rel rows hit consecutive banks (conflict-
// free), and total = 24576 + 24576 = 49152 B = default dynamic-smem limit
// (no cudaFuncSetAttribute needed).
// ---------------------------------------------------------------------------
#define ATTN_SMEM ((2 * TT * HS + HS * 256) * 4)   // 49152 bytes exactly

__global__ void __launch_bounds__(128) attn_kernel(const float* __restrict__ rel) {
    extern __shared__ float sm[];
    float* Ks  = sm;                 // TT*HS
    float* Vs  = sm + TT * HS;       // TT*HS
    float* RsT = sm + 2 * TT * HS;   // HS rows x 256 cols (cols 0..254 used)

    const int h = blockIdx.x;
    const int b = blockIdx.y;
    const size_t base = (size_t)b * (TT * NE) + (size_t)h * (TT * HS);
    const int tid = threadIdx.x;

    // Load K, V tiles: 768 float4 each
#pragma unroll
    for (int i = 0; i < 6; i++) {
        int idx = tid + i * 128;
        int r = idx / 6, c4 = idx % 6;
        *(float4*)&Ks[r * HS + c4 * 4] = *(const float4*)(g_k + base + r * HS + c4 * 4);
        *(float4*)&Vs[r * HS + c4 * 4] = *(const float4*)(g_v + base + r * HS + c4 * 4);
    }
    // rel_table transposed: RsT[d*256 + r] = rel[r*24 + d]; r-fastest iteration
    // -> conflict-free smem stores (stride-1 within warp).
    for (int idx = tid; idx < HS * 255; idx += 128) {
        int d = idx / 255, r = idx % 255;
        RsT[d * 256 + r] = rel[r * HS + d];
    }

    // Warp->row mapping, reversed on (b+h) parity to balance SMSP load
    const int w = tid >> 5;
    const int wr = ((b + h) & 1) ? (3 - w) : w;
    const int t = wr * 32 + (tid & 31);

    // Q row into registers
    float Q[HS];
    {
        const float4* qp = (const float4*)(g_q + base + (size_t)t * HS);
#pragma unroll
        for (int i = 0; i < 6; i++) {
            float4 v4 = qp[i];
            Q[i * 4 + 0] = v4.x; Q[i * 4 + 1] = v4.y;
            Q[i * 4 + 2] = v4.z; Q[i * 4 + 3] = v4.w;
        }
    }
    __syncthreads();

    const float scale = 0.20412414523193154f;   // 1/sqrt(24)
    float m = -INFINITY, l = 0.f;
    float ctx[HS];
#pragma unroll
    for (int d = 0; d < HS; d++) ctx[d] = 0.f;

    const int nch = 2 * wr + 2;   // chunks of 16 cover s <= 32*wr+31 = warp's t_max
    for (int c = 0; c < nch; c++) {
        const int s0 = c * 16;
        float sc[16];
#pragma unroll
        for (int j = 0; j < 16; j++) {
            const int s = s0 + j;
            const int rbase = t - s + 127;      // in [96, 254] for all lanes
            const float* kp = Ks + s * HS;
            float qk = 0.f, rr = 0.f;
#pragma unroll
            for (int i = 0; i < 6; i++) {       // K: LDS.128 broadcast
                float4 k4 = *(const float4*)(kp + i * 4);
                qk = fmaf(Q[i * 4 + 0], k4.x, qk);
                qk = fmaf(Q[i * 4 + 1], k4.y, qk);
                qk = fmaf(Q[i * 4 + 2], k4.z, qk);
                qk = fmaf(Q[i * 4 + 3], k4.w, qk);
            }
#pragma unroll
            for (int d = 0; d < HS; d++)        // rel: conflict-free scalar LDS
                rr = fmaf(Q[d], RsT[d * 256 + rbase], rr);
            sc[j] = (s <= t) ? fmaf(qk, scale, rr) : -INFINITY;
        }
        float cm = sc[0];
#pragma unroll
        for (int j = 1; j < 16; j++) cm = fmaxf(cm, sc[j]);
        const float mn = fmaxf(m, cm);
        const float f = __expf(m - mn);   // exp(-inf)=0 on first chunk
        l *= f;
#pragma unroll
        for (int d = 0; d < HS; d++) ctx[d] *= f;
#pragma unroll
        for (int j = 0; j < 16; j++) {
            const float p = __expf(sc[j] - mn);
            l += p;
            const float* vp = Vs + (s0 + j) * HS;
#pragma unroll
            for (int i = 0; i < 6; i++) {       // V: LDS.128 broadcast
                float4 v4 = *(const float4*)(vp + i * 4);
                ctx[i * 4 + 0] = fmaf(p, v4.x, ctx[i * 4 + 0]);
                ctx[i * 4 + 1] = fmaf(p, v4.y, ctx[i * 4 + 1]);
                ctx[i * 4 + 2] = fmaf(p, v4.z, ctx[i * 4 + 2]);
                ctx[i * 4 + 3] = fmaf(p, v4.w, ctx[i * 4 + 3]);
            }
        }
        m = mn;
    }

    const float inv = 1.f / l;
    // ctx output: transpose(0,2,1,3).reshape -> out_pre[b, t, h*24 + d]
    float* op = g_ctx + (size_t)b * (TT * NE) + (size_t)t * NE + h * HS;
#pragma unroll
    for (int i = 0; i < 6; i++) {
        float4 v4 = make_float4(ctx[i * 4 + 0] * inv, ctx[i * 4 + 1] * inv,
                                ctx[i * 4 + 2] * inv, ctx[i * 4 + 3] * inv);
        *(float4*)&op[i * 4] = v4;
    }
}

// ---------------------------------------------------------------------------
// kernel_launch: graph-capturable, allocation-free.
// Inputs: 0=x, 1=Wq, 2=Wk, 3=Wv, 4=rel_table, 5=Wproj, 6=bproj (all fp32)
// ---------------------------------------------------------------------------
extern "C" void kernel_launch(void* const* d_in, const int* in_sizes, int n_in,
                              void* d_out, int out_size) {
    const float* x   = (const float*)d_in[0];
    const float* Wq  = (const float*)d_in[1];
    const float* Wk  = (const float*)d_in[2];
    const float* Wv  = (const float*)d_in[3];
    const float* rel = (const float*)d_in[4];
    const float* Wp  = (const float*)d_in[5];
    const float* bp  = (const float*)d_in[6];
    float* out = (float*)d_out;

    const int M = in_sizes[0] / NE;   // B*T = 32768
    const int B = M / TT;             // 256

    dim3 gqkv(M / BM, NE / BN, 3);
    gemm_qkv_kernel<<<gqkv, 256>>>(x, Wq, Wk, Wv);

    attn_kernel<<<dim3(NHEADS, B), 128, ATTN_SMEM>>>(rel);

    dim3 gproj(M / BM, NE / BN, 1);
    gemm_proj_kernel<<<gproj, 256>>>(Wp, bp, out);
}

// round 6
// speedup vs baseline: 1.2506x; 1.2506x over previous
#include <cuda_runtime.h>
#include <cuda_bf16.h>
#include <math.h>
#include <stdint.h>

// Problem constants
#define NHEADS 6
#define HS     24
#define NE     144      // N_EMBD
#define TT     128
#define MAXB   256

// Scratch (allocation-free: __device__ globals)
__device__ float g_q[MAXB * TT * NE];
__device__ float g_k[MAXB * TT * NE];
__device__ float g_v[MAXB * TT * NE];
__device__ float g_ctx[MAXB * TT * NE];

// Weight images: 4 weights x [hi|lo] x [n=144][k padded to 152] bf16
#define WROW 152                       // padded k-stride (304B rows, ldsm conflict-free)
#define WIMG_SPLIT (NE * WROW)         // 21888 elems per split
#define WIMG_PER_W (2 * WIMG_SPLIT)    // 43776 elems per weight
__device__ __align__(16) __nv_bfloat16 g_wimg[4 * WIMG_PER_W];

// ===========================================================================
// PTX helpers (baseline PTX only: ldmatrix sm_75+, mma.sync bf16 sm_80+)
// ===========================================================================
__device__ __forceinline__ uint32_t s2u(const void* p) {
    uint32_t a;
    asm("{ .reg .u64 t; cvta.to.shared.u64 t, %1; cvt.u32.u64 %0, t; }"
        : "=r"(a) : "l"(p));
    return a;
}

#define LDSM4(r0, r1, r2, r3, addr)                                          \
    asm volatile("ldmatrix.sync.aligned.m8n8.x4.shared.b16 {%0,%1,%2,%3}, [%4];" \
                 : "=r"(r0), "=r"(r1), "=r"(r2), "=r"(r3) : "r"(addr))

#define MMA16816(acc, a0, a1, a2, a3, b0, b1)                                \
    asm volatile("mma.sync.aligned.m16n8k16.row.col.f32.bf16.bf16.f32 "      \
                 "{%0,%1,%2,%3}, {%4,%5,%6,%7}, {%8,%9}, {%0,%1,%2,%3};"     \
                 : "+f"((acc)[0]), "+f"((acc)[1]), "+f"((acc)[2]), "+f"((acc)[3]) \
                 : "r"(a0), "r"(a1), "r"(a2), "r"(a3), "r"(b0), "r"(b1))

// ===========================================================================
// Prep: convert + transpose weights to bf16 hi/lo images.
// W fp32 row-major [k][n]  ->  image [n][WROW] bf16 (hi split, then lo split)
// ===========================================================================
__global__ void __launch_bounds__(256) prep_w(const float* __restrict__ Wq,
                                              const float* __restrict__ Wk,
                                              const float* __restrict__ Wv,
                                              const float* __restrict__ Wp) {
    const float* W = (blockIdx.x == 0) ? Wq : (blockIdx.x == 1) ? Wk
                   : (blockIdx.x == 2) ? Wv : Wp;
    __nv_bfloat16* dst = g_wimg + blockIdx.x * WIMG_PER_W;
    for (int idx = threadIdx.x; idx < NE * NE; idx += 256) {
        int k = idx / NE, n = idx - k * NE;
        float v = W[idx];
        __nv_bfloat16 h = __float2bfloat16(v);
        __nv_bfloat16 l = __float2bfloat16(v - __bfloat162float(h));
        dst[n * WROW + k] = h;
        dst[WIMG_SPLIT + n * WROW + k] = l;
    }
}

// ===========================================================================
// Tensor-core GEMM via mma.sync: C[M,144] = A[M,144] @ W[144,144] (+bias)
// bf16 3-product split: Ahi*Whi + Ahi*Wlo + Alo*Whi, fp32 accum.
// CTA: 256 threads (8 warps), M-tile 128. Warp w: rows w*16..w*16+15, all N.
// Smem: W image copy (87552B) + A hi/lo bf16 [128][152] (77824B) = 165376B.
// ===========================================================================
#define WHOFF 0
#define WLOFF 43776
#define AHOFF 87552
#define ALOFF 126464
#define GEMM_SMEM 165376

__device__ __forceinline__ void gemm_mma_body(const float* __restrict__ A,
                                              const __nv_bfloat16* __restrict__ wimg,
                                              const float* __restrict__ bias,
                                              float* __restrict__ C) {
    extern __shared__ char sm[];
    const uint32_t su = s2u(sm);
    const int tid = threadIdx.x;
    const int lane = tid & 31;
    const int wid = tid >> 5;
    const int bm = blockIdx.x * 128;

    // --- load W image (both splits, contiguous 87552 B) as float4 ---
    {
        const float4* src = (const float4*)wimg;
        float4* dst = (float4*)sm;
        for (int i = tid; i < 5472; i += 256) dst[i] = src[i];
    }
    // --- convert A tile: 128x144 fp32 -> hi/lo bf16 [128][WROW] ---
    {
        const float* Ab = A + (size_t)bm * NE;
#pragma unroll
        for (int i = 0; i < 18; i++) {             // 4608 float4 total
            int idx4 = tid + i * 256;
            int row = idx4 / 36, c4 = idx4 - row * 36;
            float4 f = *(const float4*)(Ab + row * NE + c4 * 4);
            __nv_bfloat16 hx = __float2bfloat16(f.x), hy = __float2bfloat16(f.y);
            __nv_bfloat16 hz = __float2bfloat16(f.z), hw = __float2bfloat16(f.w);
            __nv_bfloat162 H0 = __halves2bfloat162(hx, hy);
            __nv_bfloat162 H1 = __halves2bfloat162(hz, hw);
            __nv_bfloat162 L0 = __halves2bfloat162(
                __float2bfloat16(f.x - __bfloat162float(hx)),
                __float2bfloat16(f.y - __bfloat162float(hy)));
            __nv_bfloat162 L1 = __halves2bfloat162(
                __float2bfloat16(f.z - __bfloat162float(hz)),
                __float2bfloat16(f.w - __bfloat162float(hw)));
            uint32_t off = (uint32_t)(row * WROW + c4 * 4) * 2;
            *(uint2*)(sm + AHOFF + off) = make_uint2(*(uint32_t*)&H0, *(uint32_t*)&H1);
            *(uint2*)(sm + ALOFF + off) = make_uint2(*(uint32_t*)&L0, *(uint32_t*)&L1);
        }
    }
    __syncthreads();

    // --- lane-dependent ldmatrix byte offsets ---
    // A (16x16 row-major): m = lane>>3: m0(+0,+0) m1(+8row,+0) m2(+0,+8col) m3(+8,+8)
    const int r0 = wid * 16;
    const uint32_t aoff =
        (uint32_t)((r0 + (lane & 7) + ((lane >> 3) & 1) * 8) * WROW) * 2
        + (uint32_t)((lane >> 4) * 8) * 2;
    // B from Wt[n][k]: m0(nrow+0,k+0) m1(+0,k+8) m2(+8,k+0) m3(+8,k+8)
    const uint32_t boff =
        (uint32_t)(((lane & 7) + ((lane >> 4) & 1) * 8) * WROW) * 2
        + (uint32_t)(((lane >> 3) & 1) * 8) * 2;

    float acc[18][4];
#pragma unroll
    for (int nt = 0; nt < 18; nt++)
#pragma unroll
        for (int i = 0; i < 4; i++) acc[nt][i] = 0.f;

    // --- mainloop: 3 products x 9 ksteps x 9 ntile-pairs ---
#pragma unroll 1
    for (int p = 0; p < 3; p++) {
        const uint32_t Ab = su + ((p < 2) ? AHOFF : ALOFF) + aoff;
        const uint32_t Wb = su + ((p == 1) ? WLOFF : WHOFF) + boff;
#pragma unroll 1
        for (int s = 0; s < 9; s++) {
            uint32_t a0, a1, a2, a3;
            LDSM4(a0, a1, a2, a3, Ab + s * 32);
#pragma unroll
            for (int np = 0; np < 9; np++) {
                uint32_t b0, b1, b2, b3;
                LDSM4(b0, b1, b2, b3, Wb + np * 4864 + s * 32);   // 4864 = 16*WROW*2
                MMA16816(acc[2 * np],     a0, a1, a2, a3, b0, b1);
                MMA16816(acc[2 * np + 1], a0, a1, a2, a3, b2, b3);
            }
        }
    }

    // --- epilogue: c-frag rows g,g+8 / cols 2tg ---
    const int g = lane >> 2, tg = lane & 3;
    float* Crow0 = C + (size_t)(bm + r0 + g) * NE;
    float* Crow1 = C + (size_t)(bm + r0 + g + 8) * NE;
#pragma unroll
    for (int nt = 0; nt < 18; nt++) {
        int col = nt * 8 + tg * 2;
        float b0 = bias ? bias[col] : 0.f;
        float b1 = bias ? bias[col + 1] : 0.f;
        *(float2*)(Crow0 + col) = make_float2(acc[nt][0] + b0, acc[nt][1] + b1);
        *(float2*)(Crow1 + col) = make_float2(acc[nt][2] + b0, acc[nt][3] + b1);
    }
}

__global__ void __launch_bounds__(256) gemm_qkv_mma(const float* __restrict__ x) {
    float* C = (blockIdx.y == 0) ? g_q : (blockIdx.y == 1) ? g_k : g_v;
    gemm_mma_body(x, g_wimg + blockIdx.y * WIMG_PER_W, nullptr, C);
}

__global__ void __launch_bounds__(256) gemm_proj_mma(const float* __restrict__ bp,
                                                     float* __restrict__ out) {
    gemm_mma_body(g_ctx, g_wimg + 3 * WIMG_PER_W, bp, out);
}

// ---------------------------------------------------------------------------
// Attention (unchanged, passing at R4): one block per (b,h), 128 threads,
// one t-row/thread, flash-style online softmax, rel table transposed in smem.
// ---------------------------------------------------------------------------
#define ATTN_SMEM ((2 * TT * HS + HS * 256) * 4)   // 49152 bytes

__global__ void __launch_bounds__(128) attn_kernel(const float* __restrict__ rel) {
    extern __shared__ float smf[];
    float* Ks  = smf;
    float* Vs  = smf + TT * HS;
    float* RsT = smf + 2 * TT * HS;

    const int h = blockIdx.x;
    const int b = blockIdx.y;
    const size_t base = (size_t)b * (TT * NE) + (size_t)h * (TT * HS);
    const int tid = threadIdx.x;

#pragma unroll
    for (int i = 0; i < 6; i++) {
        int idx = tid + i * 128;
        int r = idx / 6, c4 = idx % 6;
        *(float4*)&Ks[r * HS + c4 * 4] = *(const float4*)(g_k + base + r * HS + c4 * 4);
        *(float4*)&Vs[r * HS + c4 * 4] = *(const float4*)(g_v + base + r * HS + c4 * 4);
    }
    for (int idx = tid; idx < HS * 255; idx += 128) {
        int d = idx / 255, r = idx % 255;
        RsT[d * 256 + r] = rel[r * HS + d];
    }

    const int w = tid >> 5;
    const int wr = ((b + h) & 1) ? (3 - w) : w;
    const int t = wr * 32 + (tid & 31);

    float Q[HS];
    {
        const float4* qp = (const float4*)(g_q + base + (size_t)t * HS);
#pragma unroll
        for (int i = 0; i < 6; i++) {
            float4 v4 = qp[i];
            Q[i * 4 + 0] = v4.x; Q[i * 4 + 1] = v4.y;
            Q[i * 4 + 2] = v4.z; Q[i * 4 + 3] = v4.w;
        }
    }
    __syncthreads();

    const float scale = 0.20412414523193154f;
    float m = -INFINITY, l = 0.f;
    float ctx[HS];
#pragma unroll
    for (int d = 0; d < HS; d++) ctx[d] = 0.f;

    const int nch = 2 * wr + 2;
    for (int c = 0; c < nch; c++) {
        const int s0 = c * 16;
        float sc[16];
#pragma unroll
        for (int j = 0; j < 16; j++) {
            const int s = s0 + j;
            const int rbase = t - s + 127;
            const float* kp = Ks + s * HS;
            float qk = 0.f, rr = 0.f;
#pragma unroll
            for (int i = 0; i < 6; i++) {
                float4 k4 = *(const float4*)(kp + i * 4);
                qk = fmaf(Q[i * 4 + 0], k4.x, qk);
                qk = fmaf(Q[i * 4 + 1], k4.y, qk);
                qk = fmaf(Q[i * 4 + 2], k4.z, qk);
                qk = fmaf(Q[i * 4 + 3], k4.w, qk);
            }
#pragma unroll
            for (int d = 0; d < HS; d++)
                rr = fmaf(Q[d], RsT[d * 256 + rbase], rr);
            sc[j] = (s <= t) ? fmaf(qk, scale, rr) : -INFINITY;
        }
        float cm = sc[0];
#pragma unroll
        for (int j = 1; j < 16; j++) cm = fmaxf(cm, sc[j]);
        const float mn = fmaxf(m, cm);
        const float f = __expf(m - mn);
        l *= f;
#pragma unroll
        for (int d = 0; d < HS; d++) ctx[d] *= f;
#pragma unroll
        for (int j = 0; j < 16; j++) {
            const float p = __expf(sc[j] - mn);
            l += p;
            const float* vp = Vs + (s0 + j) * HS;
#pragma unroll
            for (int i = 0; i < 6; i++) {
                float4 v4 = *(const float4*)(vp + i * 4);
                ctx[i * 4 + 0] = fmaf(p, v4.x, ctx[i * 4 + 0]);
                ctx[i * 4 + 1] = fmaf(p, v4.y, ctx[i * 4 + 1]);
                ctx[i * 4 + 2] = fmaf(p, v4.z, ctx[i * 4 + 2]);
                ctx[i * 4 + 3] = fmaf(p, v4.w, ctx[i * 4 + 3]);
            }
        }
        m = mn;
    }

    const float inv = 1.f / l;
    float* op = g_ctx + (size_t)b * (TT * NE) + (size_t)t * NE + h * HS;
#pragma unroll
    for (int i = 0; i < 6; i++) {
        float4 v4 = make_float4(ctx[i * 4 + 0] * inv, ctx[i * 4 + 1] * inv,
                                ctx[i * 4 + 2] * inv, ctx[i * 4 + 3] * inv);
        *(float4*)&op[i * 4] = v4;
    }
}

// ---------------------------------------------------------------------------
// kernel_launch
// Inputs: 0=x, 1=Wq, 2=Wk, 3=Wv, 4=rel_table, 5=Wproj, 6=bproj (all fp32)
// ---------------------------------------------------------------------------
extern "C" void kernel_launch(void* const* d_in, const int* in_sizes, int n_in,
                              void* d_out, int out_size) {
    const float* x   = (const float*)d_in[0];
    const float* Wq  = (const float*)d_in[1];
    const float* Wk  = (const float*)d_in[2];
    const float* Wv  = (const float*)d_in[3];
    const float* rel = (const float*)d_in[4];
    const float* Wp  = (const float*)d_in[5];
    const float* bp  = (const float*)d_in[6];
    float* out = (float*)d_out;

    const int M = in_sizes[0] / NE;   // B*T = 32768
    const int B = M / TT;             // 256

    (void)cudaFuncSetAttribute(gemm_qkv_mma,
                               cudaFuncAttributeMaxDynamicSharedMemorySize, GEMM_SMEM);
    (void)cudaFuncSetAttribute(gemm_proj_mma,
                               cudaFuncAttributeMaxDynamicSharedMemorySize, GEMM_SMEM);

    prep_w<<<4, 256>>>(Wq, Wk, Wv, Wp);

    gemm_qkv_mma<<<dim3(M / 128, 3), 256, GEMM_SMEM>>>(x);

    attn_kernel<<<dim3(NHEADS, B), 128, ATTN_SMEM>>>(rel);

    gemm_proj_mma<<<dim3(M / 128, 1), 256, GEMM_SMEM>>>(bp, out);
}

// round 7
// speedup vs baseline: 1.6602x; 1.3275x over previous
#include <cuda_runtime.h>
#include <cuda_bf16.h>
#include <cuda_fp16.h>
#include <math.h>
#include <stdint.h>

// Problem constants
#define NHEADS 6
#define HS     24
#define NE     144      // N_EMBD
#define TT     128
#define MAXB   256

// Scratch (allocation-free: __device__ globals)
__device__ float g_q[MAXB * TT * NE];
__device__ float g_k[MAXB * TT * NE];
__device__ float g_v[MAXB * TT * NE];
__device__ float g_ctx[MAXB * TT * NE];

// Weight images: 4 weights x [hi|lo] x [n=144][k padded to 152] bf16
#define WROW 152
#define WIMG_SPLIT (NE * WROW)
#define WIMG_PER_W (2 * WIMG_SPLIT)
__device__ __align__(16) __nv_bfloat16 g_wimg[4 * WIMG_PER_W];

// ===========================================================================
// PTX helpers (baseline PTX only)
// ===========================================================================
__device__ __forceinline__ uint32_t s2u(const void* p) {
    uint32_t a;
    asm("{ .reg .u64 t; cvta.to.shared.u64 t, %1; cvt.u32.u64 %0, t; }"
        : "=r"(a) : "l"(p));
    return a;
}
#define LDSM4(r0, r1, r2, r3, addr)                                          \
    asm volatile("ldmatrix.sync.aligned.m8n8.x4.shared.b16 {%0,%1,%2,%3}, [%4];" \
                 : "=r"(r0), "=r"(r1), "=r"(r2), "=r"(r3) : "r"(addr))
#define LDSM2(r0, r1, addr)                                                  \
    asm volatile("ldmatrix.sync.aligned.m8n8.x2.shared.b16 {%0,%1}, [%2];"   \
                 : "=r"(r0), "=r"(r1) : "r"(addr))
#define LDSM4T(r0, r1, r2, r3, addr)                                         \
    asm volatile("ldmatrix.sync.aligned.m8n8.x4.trans.shared.b16 {%0,%1,%2,%3}, [%4];" \
                 : "=r"(r0), "=r"(r1), "=r"(r2), "=r"(r3) : "r"(addr))
#define LDSM2T(r0, r1, addr)                                                 \
    asm volatile("ldmatrix.sync.aligned.m8n8.x2.trans.shared.b16 {%0,%1}, [%2];" \
                 : "=r"(r0), "=r"(r1) : "r"(addr))
#define MMA16816(acc, a0, a1, a2, a3, b0, b1)                                \
    asm volatile("mma.sync.aligned.m16n8k16.row.col.f32.bf16.bf16.f32 "      \
                 "{%0,%1,%2,%3}, {%4,%5,%6,%7}, {%8,%9}, {%0,%1,%2,%3};"     \
                 : "+f"((acc)[0]), "+f"((acc)[1]), "+f"((acc)[2]), "+f"((acc)[3]) \
                 : "r"(a0), "r"(a1), "r"(a2), "r"(a3), "r"(b0), "r"(b1))

__device__ __forceinline__ void bsplit(float x, float y, uint32_t& hi, uint32_t& lo) {
    __nv_bfloat16 hx = __float2bfloat16(x), hy = __float2bfloat16(y);
    __nv_bfloat162 H = __halves2bfloat162(hx, hy);
    __nv_bfloat162 L = __halves2bfloat162(__float2bfloat16(x - __bfloat162float(hx)),
                                          __float2bfloat16(y - __bfloat162float(hy)));
    hi = *(uint32_t*)&H;
    lo = *(uint32_t*)&L;
}

// ===========================================================================
// Prep: weights -> bf16 hi/lo images, transposed [n][WROW]
// ===========================================================================
__global__ void __launch_bounds__(256) prep_w(const float* __restrict__ Wq,
                                              const float* __restrict__ Wk,
                                              const float* __restrict__ Wv,
                                              const float* __restrict__ Wp) {
    const float* W = (blockIdx.x == 0) ? Wq : (blockIdx.x == 1) ? Wk
                   : (blockIdx.x == 2) ? Wv : Wp;
    __nv_bfloat16* dst = g_wimg + blockIdx.x * WIMG_PER_W;
    for (int idx = threadIdx.x; idx < NE * NE; idx += 256) {
        int k = idx / NE, n = idx - k * NE;
        float v = W[idx];
        __nv_bfloat16 h = __float2bfloat16(v);
        __nv_bfloat16 l = __float2bfloat16(v - __bfloat162float(h));
        dst[n * WROW + k] = h;
        dst[WIMG_SPLIT + n * WROW + k] = l;
    }
}

// ===========================================================================
// Tensor-core GEMM (512 threads): C[M,144] = A[M,144] @ W (+bias)
// 16 warps: warp w -> rows (w>>1)*16 .. +16, n-half (w&1)*72.
// ===========================================================================
#define WHOFF 0
#define WLOFF 43776
#define AHOFF 87552
#define ALOFF 126464
#define GEMM_SMEM 165376
#define GT 512

__device__ __forceinline__ void gemm_mma_body(const float* __restrict__ A,
                                              const __nv_bfloat16* __restrict__ wimg,
                                              const float* __restrict__ bias,
                                              float* __restrict__ C) {
    extern __shared__ char sm[];
    const uint32_t su = s2u(sm);
    const int tid = threadIdx.x;
    const int lane = tid & 31;
    const int wid = tid >> 5;
    const int bm = blockIdx.x * 128;

    // W image copy (hi+lo, 87552 B)
    {
        const float4* src = (const float4*)wimg;
        float4* dst = (float4*)sm;
        for (int i = tid; i < 5472; i += GT) dst[i] = src[i];
    }
    // A tile convert: 128x144 fp32 -> hi/lo bf16 [128][WROW]
    {
        const float* Ab = A + (size_t)bm * NE;
#pragma unroll
        for (int i = 0; i < 9; i++) {
            int idx4 = tid + i * GT;
            int row = idx4 / 36, c4 = idx4 - row * 36;
            float4 f = *(const float4*)(Ab + row * NE + c4 * 4);
            uint32_t h0, l0, h1, l1;
            bsplit(f.x, f.y, h0, l0);
            bsplit(f.z, f.w, h1, l1);
            uint32_t off = (uint32_t)(row * WROW + c4 * 4) * 2;
            *(uint2*)(sm + AHOFF + off) = make_uint2(h0, h1);
            *(uint2*)(sm + ALOFF + off) = make_uint2(l0, l1);
        }
    }
    __syncthreads();

    const int r0 = (wid >> 1) * 16;
    const int nbase = (wid & 1) * 72;
    const uint32_t aoff =
        (uint32_t)((r0 + (lane & 7) + ((lane >> 3) & 1) * 8) * WROW) * 2
        + ((lane >> 4) & 1) * 16;
    const uint32_t boff =
        (uint32_t)((nbase + (lane & 7) + ((lane >> 4) & 1) * 8) * WROW) * 2
        + ((lane >> 3) & 1) * 16;
    const uint32_t b2off =
        (uint32_t)((nbase + 64 + (lane & 7)) * WROW) * 2
        + ((lane >> 3) & 1) * 16;

    float acc[9][4];
#pragma unroll
    for (int nt = 0; nt < 9; nt++)
#pragma unroll
        for (int i = 0; i < 4; i++) acc[nt][i] = 0.f;

#pragma unroll 1
    for (int p = 0; p < 3; p++) {
        const uint32_t Ab = su + ((p < 2) ? AHOFF : ALOFF) + aoff;
        const uint32_t Wb = su + ((p == 1) ? WLOFF : WHOFF);
#pragma unroll 1
        for (int s = 0; s < 9; s++) {
            uint32_t a0, a1, a2, a3;
            LDSM4(a0, a1, a2, a3, Ab + s * 32);
#pragma unroll
            for (int np = 0; np < 4; np++) {
                uint32_t b0, b1, b2, b3;
                LDSM4(b0, b1, b2, b3, Wb + boff + np * (16 * WROW * 2) + s * 32);
                MMA16816(acc[2 * np],     a0, a1, a2, a3, b0, b1);
                MMA16816(acc[2 * np + 1], a0, a1, a2, a3, b2, b3);
            }
            uint32_t c0, c1;
            LDSM2(c0, c1, Wb + b2off + s * 32);
            MMA16816(acc[8], a0, a1, a2, a3, c0, c1);
        }
    }

    const int g = lane >> 2, tg = lane & 3;
    float* Crow0 = C + (size_t)(bm + r0 + g) * NE;
    float* Crow1 = C + (size_t)(bm + r0 + g + 8) * NE;
#pragma unroll
    for (int nt = 0; nt < 9; nt++) {
        int col = nbase + nt * 8 + tg * 2;
        float b0 = bias ? bias[col] : 0.f;
        float b1 = bias ? bias[col + 1] : 0.f;
        *(float2*)(Crow0 + col) = make_float2(acc[nt][0] + b0, acc[nt][1] + b1);
        *(float2*)(Crow1 + col) = make_float2(acc[nt][2] + b0, acc[nt][3] + b1);
    }
}

__global__ void __launch_bounds__(GT) gemm_qkv_mma(const float* __restrict__ x) {
    float* C = (blockIdx.y == 0) ? g_q : (blockIdx.y == 1) ? g_k : g_v;
    gemm_mma_body(x, g_wimg + blockIdx.y * WIMG_PER_W, nullptr, C);
}
__global__ void __launch_bounds__(GT) gemm_proj_mma(const float* __restrict__ bp,
                                                    float* __restrict__ out) {
    gemm_mma_body(g_ctx, g_wimg + 3 * WIMG_PER_W, bp, out);
}

// ===========================================================================
// Tensorized attention. One CTA per (b,h), 256 threads (8 warps x 16 rows).
// scores[t][s] = scale*(Q.K)[t][s] + P'[t][t-s],  P'[t][u] = Q[t].rel[u+127]
// Images: bf16 [128][40] (rows 80B, conflict-free ldmatrix).
// Sbuf: fp16 [128][132] for the P' diagonal shuffle.
// ===========================================================================
#define AQH 0
#define AQL 10240
#define AKH 20480
#define AKL 30720
#define ARH 40960
#define AVH 51200
#define AVL 61440
#define ASB 71680
#define SBW 132
#define ATTN_SMEM (ASB + 128 * SBW * 2)   // 105472 B -> 2 CTAs/SM

__device__ __forceinline__ void cvt_pair_st(char* sm, int oh, int ol,
                                            uint32_t o, float4 f) {
    uint32_t h0, l0, h1, l1;
    bsplit(f.x, f.y, h0, l0);
    bsplit(f.z, f.w, h1, l1);
    *(uint2*)(sm + oh + o) = make_uint2(h0, h1);
    *(uint2*)(sm + ol + o) = make_uint2(l0, l1);
}

__global__ void __launch_bounds__(256, 2) attn_kernel(const float* __restrict__ rel) {
    extern __shared__ char sm[];
    const uint32_t su = s2u(sm);
    const int h = blockIdx.x, b = blockIdx.y;
    const size_t base = (size_t)b * (TT * NE) + (size_t)h * (TT * HS);
    const int tid = threadIdx.x;
    const int lane = tid & 31, wid = tid >> 5;

    // ---- load + convert: Q/K/V hi+lo, rel hi-only (rows 127..254) ----
#pragma unroll
    for (int i = 0; i < 3; i++) {
        int idx = tid + i * 256;          // 0..767
        int r = idx / 6, c4 = idx % 6;
        uint32_t o = (uint32_t)r * 80 + (uint32_t)c4 * 8;
        float4 f;
        f = *(const float4*)(g_q + base + r * HS + c4 * 4);
        cvt_pair_st(sm, AQH, AQL, o, f);
        f = *(const float4*)(g_k + base + r * HS + c4 * 4);
        cvt_pair_st(sm, AKH, AKL, o, f);
        f = *(const float4*)(g_v + base + r * HS + c4 * 4);
        cvt_pair_st(sm, AVH, AVL, o, f);
        f = *(const float4*)(rel + (size_t)(127 + r) * HS + c4 * 4);
        uint32_t h0, l0, h1, l1;
        bsplit(f.x, f.y, h0, l0);
        bsplit(f.z, f.w, h1, l1);
        *(uint2*)(sm + ARH + o) = make_uint2(h0, h1);
    }
    // zero pad cols 24..31 (bytes 48..63) of all 7 images
    for (int idx = tid; idx < 896; idx += 256) {
        int img = idx >> 7, r = idx & 127;
        *(uint4*)(sm + img * 10240 + r * 80 + 48) = make_uint4(0, 0, 0, 0);
    }
    __syncthreads();

    const int r0 = wid * 16;
    const int g = lane >> 2, tg = lane & 3;
    const int t0 = r0 + g, t1 = t0 + 8;
    const uint32_t aoff =
        (uint32_t)((r0 + (lane & 7) + ((lane >> 3) & 1) * 8) * 80)
        + ((lane >> 4) & 1) * 16;
    const uint32_t boff =
        (uint32_t)(((lane & 7) + ((lane >> 4) & 1) * 8) * 80)
        + ((lane >> 3) & 1) * 16;

    __half* SB = (__half*)(sm + ASB);

    // ---- P' GEMM: Qhi @ relhi^T (single product) ----
    {
        float pa[16][4];
#pragma unroll
        for (int nt = 0; nt < 16; nt++)
#pragma unroll
            for (int i = 0; i < 4; i++) pa[nt][i] = 0.f;
#pragma unroll
        for (int s = 0; s < 2; s++) {
            uint32_t a0, a1, a2, a3;
            LDSM4(a0, a1, a2, a3, su + AQH + aoff + s * 32);
#pragma unroll
            for (int np = 0; np < 8; np++) {
                uint32_t b0, b1, b2, b3;
                LDSM4(b0, b1, b2, b3, su + ARH + boff + np * 1280 + s * 32);
                MMA16816(pa[2 * np],     a0, a1, a2, a3, b0, b1);
                MMA16816(pa[2 * np + 1], a0, a1, a2, a3, b2, b3);
            }
        }
        // scatter P'[t][u] -> SB[t][t-u] (fp16)
#pragma unroll
        for (int nt = 0; nt < 16; nt++) {
            int u = nt * 8 + tg * 2;
            if (u     <= t0) SB[t0 * SBW + (t0 - u)]     = __float2half_rn(pa[nt][0]);
            if (u + 1 <= t0) SB[t0 * SBW + (t0 - u - 1)] = __float2half_rn(pa[nt][1]);
            if (u     <= t1) SB[t1 * SBW + (t1 - u)]     = __float2half_rn(pa[nt][2]);
            if (u + 1 <= t1) SB[t1 * SBW + (t1 - u - 1)] = __float2half_rn(pa[nt][3]);
        }
    }
    __syncwarp();

    // ---- S1 GEMM: Qhi.Khi + Qhi.Klo + Qlo.Khi ----
    float sa[16][4];
#pragma unroll
    for (int nt = 0; nt < 16; nt++)
#pragma unroll
        for (int i = 0; i < 4; i++) sa[nt][i] = 0.f;
#pragma unroll 1
    for (int p = 0; p < 3; p++) {
        const uint32_t Ai = su + ((p == 2) ? AQL : AQH) + aoff;
        const uint32_t Bi = su + ((p == 1) ? AKL : AKH) + boff;
#pragma unroll
        for (int s = 0; s < 2; s++) {
            uint32_t a0, a1, a2, a3;
            LDSM4(a0, a1, a2, a3, Ai + s * 32);
#pragma unroll
            for (int np = 0; np < 8; np++) {
                uint32_t b0, b1, b2, b3;
                LDSM4(b0, b1, b2, b3, Bi + np * 1280 + s * 32);
                MMA16816(sa[2 * np],     a0, a1, a2, a3, b0, b1);
                MMA16816(sa[2 * np + 1], a0, a1, a2, a3, b2, b3);
            }
        }
    }

    // ---- merge + causal mask + softmax (registers + quad shuffles) ----
    const float scale = 0.20412414523193154f;   // 1/sqrt(24)
    float m0 = -INFINITY, m1 = -INFINITY;
#pragma unroll
    for (int nt = 0; nt < 16; nt++) {
        int s = nt * 8 + tg * 2;
        __half2 q0 = *(__half2*)(SB + t0 * SBW + s);
        __half2 q1 = *(__half2*)(SB + t1 * SBW + s);
        float v;
        v = (s     <= t0) ? fmaf(scale, sa[nt][0], __low2float(q0))  : -INFINITY;
        sa[nt][0] = v; m0 = fmaxf(m0, v);
        v = (s + 1 <= t0) ? fmaf(scale, sa[nt][1], __high2float(q0)) : -INFINITY;
        sa[nt][1] = v; m0 = fmaxf(m0, v);
        v = (s     <= t1) ? fmaf(scale, sa[nt][2], __low2float(q1))  : -INFINITY;
        sa[nt][2] = v; m1 = fmaxf(m1, v);
        v = (s + 1 <= t1) ? fmaf(scale, sa[nt][3], __high2float(q1)) : -INFINITY;
        sa[nt][3] = v; m1 = fmaxf(m1, v);
    }
    m0 = fmaxf(m0, __shfl_xor_sync(0xffffffffu, m0, 1));
    m0 = fmaxf(m0, __shfl_xor_sync(0xffffffffu, m0, 2));
    m1 = fmaxf(m1, __shfl_xor_sync(0xffffffffu, m1, 1));
    m1 = fmaxf(m1, __shfl_xor_sync(0xffffffffu, m1, 2));
    float l0 = 0.f, l1 = 0.f;
#pragma unroll
    for (int nt = 0; nt < 16; nt++) {
        sa[nt][0] = __expf(sa[nt][0] - m0); l0 += sa[nt][0];
        sa[nt][1] = __expf(sa[nt][1] - m0); l0 += sa[nt][1];
        sa[nt][2] = __expf(sa[nt][2] - m1); l1 += sa[nt][2];
        sa[nt][3] = __expf(sa[nt][3] - m1); l1 += sa[nt][3];
    }
    l0 += __shfl_xor_sync(0xffffffffu, l0, 1);
    l0 += __shfl_xor_sync(0xffffffffu, l0, 2);
    l1 += __shfl_xor_sync(0xffffffffu, l1, 1);
    l1 += __shfl_xor_sync(0xffffffffu, l1, 2);
    const float inv0 = 1.f / l0, inv1 = 1.f / l1;

    // ---- O GEMM: Ahi.Vhi + Alo.Vhi + Ahi.Vlo; A-frags built from sa regs ----
    float oa[3][4];
#pragma unroll
    for (int nt = 0; nt < 3; nt++)
#pragma unroll
        for (int i = 0; i < 4; i++) oa[nt][i] = 0.f;
    const uint32_t vrow = (uint32_t)(((lane & 7) + ((lane >> 3) & 1) * 8) * 80);
    const uint32_t vt4 = vrow + ((lane >> 4) & 1) * 16;
    const uint32_t vt2 = vrow + 32;
#pragma unroll
    for (int i = 0; i < 8; i++) {
        uint32_t ah[4], al[4];
        bsplit(sa[2 * i][0],     sa[2 * i][1],     ah[0], al[0]);
        bsplit(sa[2 * i][2],     sa[2 * i][3],     ah[1], al[1]);
        bsplit(sa[2 * i + 1][0], sa[2 * i + 1][1], ah[2], al[2]);
        bsplit(sa[2 * i + 1][2], sa[2 * i + 1][3], ah[3], al[3]);
        uint32_t bh0, bh1, bh2, bh3, bh4, bh5;
        uint32_t bl0, bl1, bl2, bl3, bl4, bl5;
        LDSM4T(bh0, bh1, bh2, bh3, su + AVH + i * 1280 + vt4);
        LDSM2T(bh4, bh5,           su + AVH + i * 1280 + vt2);
        LDSM4T(bl0, bl1, bl2, bl3, su + AVL + i * 1280 + vt4);
        LDSM2T(bl4, bl5,           su + AVL + i * 1280 + vt2);
        MMA16816(oa[0], ah[0], ah[1], ah[2], ah[3], bh0, bh1);
        MMA16816(oa[0], al[0], al[1], al[2], al[3], bh0, bh1);
        MMA16816(oa[0], ah[0], ah[1], ah[2], ah[3], bl0, bl1);
        MMA16816(oa[1], ah[0], ah[1], ah[2], ah[3], bh2, bh3);
        MMA16816(oa[1], al[0], al[1], al[2], al[3], bh2, bh3);
        MMA16816(oa[1], ah[0], ah[1], ah[2], ah[3], bl2, bl3);
        MMA16816(oa[2], ah[0], ah[1], ah[2], ah[3], bh4, bh5);
        MMA16816(oa[2], al[0], al[1], al[2], al[3], bh4, bh5);
        MMA16816(oa[2], ah[0], ah[1], ah[2], ah[3], bl4, bl5);
    }

    // ---- epilogue: ctx/l -> g_ctx[b, t, h*24+d] ----
    float* o0 = g_ctx + (size_t)b * (TT * NE) + (size_t)t0 * NE + h * HS;
    float* o1 = g_ctx + (size_t)b * (TT * NE) + (size_t)t1 * NE + h * HS;
#pragma unroll
    for (int nt = 0; nt < 3; nt++) {
        int d = nt * 8 + tg * 2;
        *(float2*)(o0 + d) = make_float2(oa[nt][0] * inv0, oa[nt][1] * inv0);
        *(float2*)(o1 + d) = make_float2(oa[nt][2] * inv1, oa[nt][3] * inv1);
    }
}

// ---------------------------------------------------------------------------
// kernel_launch
// Inputs: 0=x, 1=Wq, 2=Wk, 3=Wv, 4=rel_table, 5=Wproj, 6=bproj (all fp32)
// ---------------------------------------------------------------------------
extern "C" void kernel_launch(void* const* d_in, const int* in_sizes, int n_in,
                              void* d_out, int out_size) {
    const float* x   = (const float*)d_in[0];
    const float* Wq  = (const float*)d_in[1];
    const float* Wk  = (const float*)d_in[2];
    const float* Wv  = (const float*)d_in[3];
    const float* rel = (const float*)d_in[4];
    const float* Wp  = (const float*)d_in[5];
    const float* bp  = (const float*)d_in[6];
    float* out = (float*)d_out;

    const int M = in_sizes[0] / NE;   // 32768
    const int B = M / TT;             // 256

    (void)cudaFuncSetAttribute(gemm_qkv_mma,
                               cudaFuncAttributeMaxDynamicSharedMemorySize, GEMM_SMEM);
    (void)cudaFuncSetAttribute(gemm_proj_mma,
                               cudaFuncAttributeMaxDynamicSharedMemorySize, GEMM_SMEM);
    (void)cudaFuncSetAttribute(attn_kernel,
                               cudaFuncAttributeMaxDynamicSharedMemorySize, ATTN_SMEM);

    prep_w<<<4, 256>>>(Wq, Wk, Wv, Wp);

    gemm_qkv_mma<<<dim3(M / 128, 3), GT, GEMM_SMEM>>>(x);

    attn_kernel<<<dim3(NHEADS, B), 256, ATTN_SMEM>>>(rel);

    gemm_proj_mma<<<dim3(M / 128, 1), GT, GEMM_SMEM>>>(bp, out);
}

// round 12
// speedup vs baseline: 1.8708x; 1.1269x over previous
#include <cuda_runtime.h>
#include <cuda_bf16.h>
#include <cuda_fp16.h>
#include <math.h>
#include <stdint.h>

// Problem constants
#define NHEADS 6
#define HS     24
#define NE     144      // N_EMBD
#define TT     128
#define MAXB   256

// Scratch (allocation-free: __device__ globals)
__device__ float g_q[MAXB * TT * NE];
__device__ float g_k[MAXB * TT * NE];
__device__ float g_v[MAXB * TT * NE];
__device__ float g_ctx[MAXB * TT * NE];

// Weight images: 4 weights x [hi|lo] x [n=144][k padded to 152] bf16
#define WROW 152
#define WIMG_SPLIT (NE * WROW)
#define WIMG_PER_W (2 * WIMG_SPLIT)
__device__ __align__(16) __nv_bfloat16 g_wimg[4 * WIMG_PER_W];

// ===========================================================================
// PTX helpers (baseline PTX only)
// ===========================================================================
__device__ __forceinline__ uint32_t s2u(const void* p) {
    uint32_t a;
    asm("{ .reg .u64 t; cvta.to.shared.u64 t, %1; cvt.u32.u64 %0, t; }"
        : "=r"(a) : "l"(p));
    return a;
}
#define LDSM4(r0, r1, r2, r3, addr)                                          \
    asm volatile("ldmatrix.sync.aligned.m8n8.x4.shared.b16 {%0,%1,%2,%3}, [%4];" \
                 : "=r"(r0), "=r"(r1), "=r"(r2), "=r"(r3) : "r"(addr))
#define LDSM2(r0, r1, addr)                                                  \
    asm volatile("ldmatrix.sync.aligned.m8n8.x2.shared.b16 {%0,%1}, [%2];"   \
                 : "=r"(r0), "=r"(r1) : "r"(addr))
#define LDSM4T(r0, r1, r2, r3, addr)                                         \
    asm volatile("ldmatrix.sync.aligned.m8n8.x4.trans.shared.b16 {%0,%1,%2,%3}, [%4];" \
                 : "=r"(r0), "=r"(r1), "=r"(r2), "=r"(r3) : "r"(addr))
#define LDSM2T(r0, r1, addr)                                                 \
    asm volatile("ldmatrix.sync.aligned.m8n8.x2.trans.shared.b16 {%0,%1}, [%2];" \
                 : "=r"(r0), "=r"(r1) : "r"(addr))
#define MMA16816(acc, a0, a1, a2, a3, b0, b1)                                \
    asm volatile("mma.sync.aligned.m16n8k16.row.col.f32.bf16.bf16.f32 "      \
                 "{%0,%1,%2,%3}, {%4,%5,%6,%7}, {%8,%9}, {%0,%1,%2,%3};"     \
                 : "+f"((acc)[0]), "+f"((acc)[1]), "+f"((acc)[2]), "+f"((acc)[3]) \
                 : "r"(a0), "r"(a1), "r"(a2), "r"(a3), "r"(b0), "r"(b1))

__device__ __forceinline__ void bsplit(float x, float y, uint32_t& hi, uint32_t& lo) {
    __nv_bfloat16 hx = __float2bfloat16(x), hy = __float2bfloat16(y);
    __nv_bfloat162 H = __halves2bfloat162(hx, hy);
    __nv_bfloat162 L = __halves2bfloat162(__float2bfloat16(x - __bfloat162float(hx)),
                                          __float2bfloat16(y - __bfloat162float(hy)));
    hi = *(uint32_t*)&H;
    lo = *(uint32_t*)&L;
}

// ===========================================================================
// Prep: weights -> bf16 hi/lo images, transposed [n][WROW]
// ===========================================================================
__global__ void __launch_bounds__(256) prep_w(const float* __restrict__ Wq,
                                              const float* __restrict__ Wk,
                                              const float* __restrict__ Wv,
                                              const float* __restrict__ Wp) {
    const float* W = (blockIdx.x == 0) ? Wq : (blockIdx.x == 1) ? Wk
                   : (blockIdx.x == 2) ? Wv : Wp;
    __nv_bfloat16* dst = g_wimg + blockIdx.x * WIMG_PER_W;
    for (int idx = threadIdx.x; idx < NE * NE; idx += 256) {
        int k = idx / NE, n = idx - k * NE;
        float v = W[idx];
        __nv_bfloat16 h = __float2bfloat16(v);
        __nv_bfloat16 l = __float2bfloat16(v - __bfloat162float(h));
        dst[n * WROW + k] = h;
        dst[WIMG_SPLIT + n * WROW + k] = l;
    }
}

// ===========================================================================
// Tensor-core GEMM v2: k-outer, A direct from global (no A smem).
// 256 threads (8 warps: 4 row-stripes x 2 n-halves), M-tile 64.
// Smem = W image only (87552 B) -> 2 CTAs/SM.
// ===========================================================================
#define WLOFF 43776
#define GEMM_SMEM 87552

__device__ __forceinline__ void gemm_mma_body(const float* __restrict__ A,
                                              const __nv_bfloat16* __restrict__ wimg,
                                              const float* __restrict__ bias,
                                              float* __restrict__ C) {
    extern __shared__ char sm[];
    const uint32_t su = s2u(sm);
    const int tid = threadIdx.x;
    const int lane = tid & 31;
    const int wid = tid >> 5;
    const int bm = blockIdx.x * 64;

    // W image copy (hi+lo, 87552 B)
    {
        const float4* src = (const float4*)wimg;
        float4* dst = (float4*)sm;
        for (int i = tid; i < 5472; i += 256) dst[i] = src[i];
    }
    __syncthreads();

    const int r0 = (wid >> 1) * 16;
    const int nbase = (wid & 1) * 72;
    const float* Ar  = A + (size_t)(bm + r0 + (lane >> 2)) * NE;
    const float* Ar8 = Ar + 8 * NE;
    const int kcol = (lane & 3) * 2;

    const uint32_t boff =
        (uint32_t)((nbase + (lane & 7) + ((lane >> 4) & 1) * 8) * WROW) * 2
        + ((lane >> 3) & 1) * 16;
    const uint32_t b2off =
        (uint32_t)((nbase + 64 + (lane & 7)) * WROW) * 2
        + ((lane >> 3) & 1) * 16;

    float acc[9][4];
#pragma unroll
    for (int nt = 0; nt < 9; nt++)
#pragma unroll
        for (int i = 0; i < 4; i++) acc[nt][i] = 0.f;

#pragma unroll
    for (int s = 0; s < 9; s++) {
        const int k0 = s * 16;
        float2 f00 = *(const float2*)(Ar  + k0 + kcol);
        float2 f10 = *(const float2*)(Ar8 + k0 + kcol);
        float2 f01 = *(const float2*)(Ar  + k0 + 8 + kcol);
        float2 f11 = *(const float2*)(Ar8 + k0 + 8 + kcol);
        uint32_t ah0, al0, ah1, al1, ah2, al2, ah3, al3;
        bsplit(f00.x, f00.y, ah0, al0);
        bsplit(f10.x, f10.y, ah1, al1);
        bsplit(f01.x, f01.y, ah2, al2);
        bsplit(f11.x, f11.y, ah3, al3);

#pragma unroll
        for (int np = 0; np < 4; np++) {
            const uint32_t wo = boff + np * (16 * WROW * 2) + s * 32;
            uint32_t bh0, bh1, bh2, bh3, bl0, bl1, bl2, bl3;
            LDSM4(bh0, bh1, bh2, bh3, su + wo);
            LDSM4(bl0, bl1, bl2, bl3, su + WLOFF + wo);
            MMA16816(acc[2 * np],     ah0, ah1, ah2, ah3, bh0, bh1);
            MMA16816(acc[2 * np],     al0, al1, al2, al3, bh0, bh1);
            MMA16816(acc[2 * np],     ah0, ah1, ah2, ah3, bl0, bl1);
            MMA16816(acc[2 * np + 1], ah0, ah1, ah2, ah3, bh2, bh3);
            MMA16816(acc[2 * np + 1], al0, al1, al2, al3, bh2, bh3);
            MMA16816(acc[2 * np + 1], ah0, ah1, ah2, ah3, bl2, bl3);
        }
        {
            uint32_t ch0, ch1, cl0, cl1;
            LDSM2(ch0, ch1, su + b2off + s * 32);
            LDSM2(cl0, cl1, su + WLOFF + b2off + s * 32);
            MMA16816(acc[8], ah0, ah1, ah2, ah3, ch0, ch1);
            MMA16816(acc[8], al0, al1, al2, al3, ch0, ch1);
            MMA16816(acc[8], ah0, ah1, ah2, ah3, cl0, cl1);
        }
    }

    const int g = lane >> 2, tg = lane & 3;
    float* Crow0 = C + (size_t)(bm + r0 + g) * NE;
    float* Crow1 = C + (size_t)(bm + r0 + g + 8) * NE;
#pragma unroll
    for (int nt = 0; nt < 9; nt++) {
        int col = nbase + nt * 8 + tg * 2;
        float b0 = bias ? bias[col] : 0.f;
        float b1 = bias ? bias[col + 1] : 0.f;
        *(float2*)(Crow0 + col) = make_float2(acc[nt][0] + b0, acc[nt][1] + b1);
        *(float2*)(Crow1 + col) = make_float2(acc[nt][2] + b0, acc[nt][3] + b1);
    }
}

__global__ void __launch_bounds__(256, 2) gemm_qkv_mma(const float* __restrict__ x) {
    float* C = (blockIdx.y == 0) ? g_q : (blockIdx.y == 1) ? g_k : g_v;
    gemm_mma_body(x, g_wimg + blockIdx.y * WIMG_PER_W, nullptr, C);
}
__global__ void __launch_bounds__(256, 2) gemm_proj_mma(const float* __restrict__ bp,
                                                        float* __restrict__ out) {
    gemm_mma_body(g_ctx, g_wimg + 3 * WIMG_PER_W, bp, out);
}

// ===========================================================================
// Tensorized attention (unchanged from R7, passing).
// ===========================================================================
#define AQH 0
#define AQL 10240
#define AKH 20480
#define AKL 30720
#define ARH 40960
#define AVH 51200
#define AVL 61440
#define ASB 71680
#define SBW 132
#define ATTN_SMEM (ASB + 128 * SBW * 2)   // 105472 B -> 2 CTAs/SM

__device__ __forceinline__ void cvt_pair_st(char* sm, int oh, int ol,
                                            uint32_t o, float4 f) {
    uint32_t h0, l0, h1, l1;
    bsplit(f.x, f.y, h0, l0);
    bsplit(f.z, f.w, h1, l1);
    *(uint2*)(sm + oh + o) = make_uint2(h0, h1);
    *(uint2*)(sm + ol + o) = make_uint2(l0, l1);
}

__global__ void __launch_bounds__(256, 2) attn_kernel(const float* __restrict__ rel) {
    extern __shared__ char sm[];
    const uint32_t su = s2u(sm);
    const int h = blockIdx.x, b = blockIdx.y;
    const size_t base = (size_t)b * (TT * NE) + (size_t)h * (TT * HS);
    const int tid = threadIdx.x;
    const int lane = tid & 31, wid = tid >> 5;

#pragma unroll
    for (int i = 0; i < 3; i++) {
        int idx = tid + i * 256;
        int r = idx / 6, c4 = idx % 6;
        uint32_t o = (uint32_t)r * 80 + (uint32_t)c4 * 8;
        float4 f;
        f = *(const float4*)(g_q + base + r * HS + c4 * 4);
        cvt_pair_st(sm, AQH, AQL, o, f);
        f = *(const float4*)(g_k + base + r * HS + c4 * 4);
        cvt_pair_st(sm, AKH, AKL, o, f);
        f = *(const float4*)(g_v + base + r * HS + c4 * 4);
        cvt_pair_st(sm, AVH, AVL, o, f);
        f = *(const float4*)(rel + (size_t)(127 + r) * HS + c4 * 4);
        uint32_t h0, l0, h1, l1;
        bsplit(f.x, f.y, h0, l0);
        bsplit(f.z, f.w, h1, l1);
        *(uint2*)(sm + ARH + o) = make_uint2(h0, h1);
    }
    for (int idx = tid; idx < 896; idx += 256) {
        int img = idx >> 7, r = idx & 127;
        *(uint4*)(sm + img * 10240 + r * 80 + 48) = make_uint4(0, 0, 0, 0);
    }
    __syncthreads();

    const int r0 = wid * 16;
    const int g = lane >> 2, tg = lane & 3;
    const int t0 = r0 + g, t1 = t0 + 8;
    const uint32_t aoff =
        (uint32_t)((r0 + (lane & 7) + ((lane >> 3) & 1) * 8) * 80)
        + ((lane >> 4) & 1) * 16;
    const uint32_t boff =
        (uint32_t)(((lane & 7) + ((lane >> 4) & 1) * 8) * 80)
        + ((lane >> 3) & 1) * 16;

    __half* SB = (__half*)(sm + ASB);

    // P' GEMM: Qhi @ relhi^T
    {
        float pa[16][4];
#pragma unroll
        for (int nt = 0; nt < 16; nt++)
#pragma unroll
            for (int i = 0; i < 4; i++) pa[nt][i] = 0.f;
#pragma unroll
        for (int s = 0; s < 2; s++) {
            uint32_t a0, a1, a2, a3;
            LDSM4(a0, a1, a2, a3, su + AQH + aoff + s * 32);
#pragma unroll
            for (int np = 0; np < 8; np++) {
                uint32_t b0, b1, b2, b3;
                LDSM4(b0, b1, b2, b3, su + ARH + boff + np * 1280 + s * 32);
                MMA16816(pa[2 * np],     a0, a1, a2, a3, b0, b1);
                MMA16816(pa[2 * np + 1], a0, a1, a2, a3, b2, b3);
            }
        }
#pragma unroll
        for (int nt = 0; nt < 16; nt++) {
            int u = nt * 8 + tg * 2;
            if (u     <= t0) SB[t0 * SBW + (t0 - u)]     = __float2half_rn(pa[nt][0]);
            if (u + 1 <= t0) SB[t0 * SBW + (t0 - u - 1)] = __float2half_rn(pa[nt][1]);
            if (u     <= t1) SB[t1 * SBW + (t1 - u)]     = __float2half_rn(pa[nt][2]);
            if (u + 1 <= t1) SB[t1 * SBW + (t1 - u - 1)] = __float2half_rn(pa[nt][3]);
        }
    }
    __syncwarp();

    // S1 GEMM: Qhi.Khi + Qhi.Klo + Qlo.Khi
    float sa[16][4];
#pragma unroll
    for (int nt = 0; nt < 16; nt++)
#pragma unroll
        for (int i = 0; i < 4; i++) sa[nt][i] = 0.f;
#pragma unroll 1
    for (int p = 0; p < 3; p++) {
        const uint32_t Ai = su + ((p == 2) ? AQL : AQH) + aoff;
        const uint32_t Bi = su + ((p == 1) ? AKL : AKH) + boff;
#pragma unroll
        for (int s = 0; s < 2; s++) {
            uint32_t a0, a1, a2, a3;
            LDSM4(a0, a1, a2, a3, Ai + s * 32);
#pragma unroll
            for (int np = 0; np < 8; np++) {
                uint32_t b0, b1, b2, b3;
                LDSM4(b0, b1, b2, b3, Bi + np * 1280 + s * 32);
                MMA16816(sa[2 * np],     a0, a1, a2, a3, b0, b1);
                MMA16816(sa[2 * np + 1], a0, a1, a2, a3, b2, b3);
            }
        }
    }

    // merge + mask + softmax
    const float scale = 0.20412414523193154f;
    float m0 = -INFINITY, m1 = -INFINITY;
#pragma unroll
    for (int nt = 0; nt < 16; nt++) {
        int s = nt * 8 + tg * 2;
        __half2 q0 = *(__half2*)(SB + t0 * SBW + s);
        __half2 q1 = *(__half2*)(SB + t1 * SBW + s);
        float v;
        v = (s     <= t0) ? fmaf(scale, sa[nt][0], __low2float(q0))  : -INFINITY;
        sa[nt][0] = v; m0 = fmaxf(m0, v);
        v = (s + 1 <= t0) ? fmaf(scale, sa[nt][1], __high2float(q0)) : -INFINITY;
        sa[nt][1] = v; m0 = fmaxf(m0, v);
        v = (s     <= t1) ? fmaf(scale, sa[nt][2], __low2float(q1))  : -INFINITY;
        sa[nt][2] = v; m1 = fmaxf(m1, v);
        v = (s + 1 <= t1) ? fmaf(scale, sa[nt][3], __high2float(q1)) : -INFINITY;
        sa[nt][3] = v; m1 = fmaxf(m1, v);
    }
    m0 = fmaxf(m0, __shfl_xor_sync(0xffffffffu, m0, 1));
    m0 = fmaxf(m0, __shfl_xor_sync(0xffffffffu, m0, 2));
    m1 = fmaxf(m1, __shfl_xor_sync(0xffffffffu, m1, 1));
    m1 = fmaxf(m1, __shfl_xor_sync(0xffffffffu, m1, 2));
    float l0 = 0.f, l1 = 0.f;
#pragma unroll
    for (int nt = 0; nt < 16; nt++) {
        sa[nt][0] = __expf(sa[nt][0] - m0); l0 += sa[nt][0];
        sa[nt][1] = __expf(sa[nt][1] - m0); l0 += sa[nt][1];
        sa[nt][2] = __expf(sa[nt][2] - m1); l1 += sa[nt][2];
        sa[nt][3] = __expf(sa[nt][3] - m1); l1 += sa[nt][3];
    }
    l0 += __shfl_xor_sync(0xffffffffu, l0, 1);
    l0 += __shfl_xor_sync(0xffffffffu, l0, 2);
    l1 += __shfl_xor_sync(0xffffffffu, l1, 1);
    l1 += __shfl_xor_sync(0xffffffffu, l1, 2);
    const float inv0 = 1.f / l0, inv1 = 1.f / l1;

    // O GEMM
    float oa[3][4];
#pragma unroll
    for (int nt = 0; nt < 3; nt++)
#pragma unroll
        for (int i = 0; i < 4; i++) oa[nt][i] = 0.f;
    const uint32_t vrow = (uint32_t)(((lane & 7) + ((lane >> 3) & 1) * 8) * 80);
    const uint32_t vt4 = vrow + ((lane >> 4) & 1) * 16;
    const uint32_t vt2 = vrow + 32;
#pragma unroll
    for (int i = 0; i < 8; i++) {
        uint32_t ah[4], al[4];
        bsplit(sa[2 * i][0],     sa[2 * i][1],     ah[0], al[0]);
        bsplit(sa[2 * i][2],     sa[2 * i][3],     ah[1], al[1]);
        bsplit(sa[2 * i + 1][0], sa[2 * i + 1][1], ah[2], al[2]);
        bsplit(sa[2 * i + 1][2], sa[2 * i + 1][3], ah[3], al[3]);
        uint32_t bh0, bh1, bh2, bh3, bh4, bh5;
        uint32_t bl0, bl1, bl2, bl3, bl4, bl5;
        LDSM4T(bh0, bh1, bh2, bh3, su + AVH + i * 1280 + vt4);
        LDSM2T(bh4, bh5,           su + AVH + i * 1280 + vt2);
        LDSM4T(bl0, bl1, bl2, bl3, su + AVL + i * 1280 + vt4);
        LDSM2T(bl4, bl5,           su + AVL + i * 1280 + vt2);
        MMA16816(oa[0], ah[0], ah[1], ah[2], ah[3], bh0, bh1);
        MMA16816(oa[0], al[0], al[1], al[2], al[3], bh0, bh1);
        MMA16816(oa[0], ah[0], ah[1], ah[2], ah[3], bl0, bl1);
        MMA16816(oa[1], ah[0], ah[1], ah[2], ah[3], bh2, bh3);
        MMA16816(oa[1], al[0], al[1], al[2], al[3], bh2, bh3);
        MMA16816(oa[1], ah[0], ah[1], ah[2], ah[3], bl2, bl3);
        MMA16816(oa[2], ah[0], ah[1], ah[2], ah[3], bh4, bh5);
        MMA16816(oa[2], al[0], al[1], al[2], al[3], bh4, bh5);
        MMA16816(oa[2], ah[0], ah[1], ah[2], ah[3], bl4, bl5);
    }

    float* o0 = g_ctx + (size_t)b * (TT * NE) + (size_t)t0 * NE + h * HS;
    float* o1 = g_ctx + (size_t)b * (TT * NE) + (size_t)t1 * NE + h * HS;
#pragma unroll
    for (int nt = 0; nt < 3; nt++) {
        int d = nt * 8 + tg * 2;
        *(float2*)(o0 + d) = make_float2(oa[nt][0] * inv0, oa[nt][1] * inv0);
        *(float2*)(o1 + d) = make_float2(oa[nt][2] * inv1, oa[nt][3] * inv1);
    }
}

// ---------------------------------------------------------------------------
// kernel_launch
// Inputs: 0=x, 1=Wq, 2=Wk, 3=Wv, 4=rel_table, 5=Wproj, 6=bproj (all fp32)
// ---------------------------------------------------------------------------
extern "C" void kernel_launch(void* const* d_in, const int* in_sizes, int n_in,
                              void* d_out, int out_size) {
    const float* x   = (const float*)d_in[0];
    const float* Wq  = (const float*)d_in[1];
    const float* Wk  = (const float*)d_in[2];
    const float* Wv  = (const float*)d_in[3];
    const float* rel = (const float*)d_in[4];
    const float* Wp  = (const float*)d_in[5];
    const float* bp  = (const float*)d_in[6];
    float* out = (float*)d_out;

    const int M = in_sizes[0] / NE;   // 32768
    const int B = M / TT;             // 256

    (void)cudaFuncSetAttribute(gemm_qkv_mma,
                               cudaFuncAttributeMaxDynamicSharedMemorySize, GEMM_SMEM);
    (void)cudaFuncSetAttribute(gemm_proj_mma,
                               cudaFuncAttributeMaxDynamicSharedMemorySize, GEMM_SMEM);
    (void)cudaFuncSetAttribute(attn_kernel,
                               cudaFuncAttributeMaxDynamicSharedMemorySize, ATTN_SMEM);

    prep_w<<<4, 256>>>(Wq, Wk, Wv, Wp);

    gemm_qkv_mma<<<dim3(M / 64, 3), 256, GEMM_SMEM>>>(x);

    attn_kernel<<<dim3(NHEADS, B), 256, ATTN_SMEM>>>(rel);

    gemm_proj_mma<<<dim3(M / 64, 1), 256, GEMM_SMEM>>>(bp, out);
}